// round 2
// baseline (speedup 1.0000x reference)
#include <cuda_runtime.h>

// Problem constants
// B=64, S=2048, D=64, E=64, H=512, F=4, V=32000
#define TOKENS (64 * 2048)
#define NBLOCKS (TOKENS / 32)

__device__ float g_logdet[4];

// ---------------------------------------------------------------------------
// helpers
// ---------------------------------------------------------------------------
__device__ __forceinline__ unsigned long long dup2(float a) {
    unsigned long long r;
    unsigned int ai = __float_as_uint(a);
    asm("mov.b64 %0, {%1, %1};" : "=l"(r) : "r"(ai));
    return r;
}
__device__ __forceinline__ void fma2(unsigned long long& d, unsigned long long a,
                                     unsigned long long b) {
    asm("fma.rn.f32x2 %0, %1, %2, %0;" : "+l"(d) : "l"(a), "l"(b));
}
__device__ __forceinline__ float2 unpk(unsigned long long v) {
    unsigned int lo, hi;
    asm("mov.b64 {%0, %1}, %2;" : "=r"(lo), "=r"(hi) : "l"(v));
    float2 r;
    r.x = __uint_as_float(lo);
    r.y = __uint_as_float(hi);
    return r;
}
__device__ __forceinline__ float gelu_exact(float x) {
    return 0.5f * x * (1.0f + erff(x * 0.70710678118654752440f));
}
// copy 4096 floats (16KB) global -> smem, 256 threads, float4
__device__ __forceinline__ void copy4k(float* dst, const float* src, int tid) {
    const float4* s = (const float4*)src;
    float4* d = (float4*)dst;
#pragma unroll
    for (int i = 0; i < 4; i++) d[tid + 256 * i] = s[tid + 256 * i];
}

// ---------------------------------------------------------------------------
// slogdet of the 4 conv matrices (64x64 LU w/ partial pivoting)
// ---------------------------------------------------------------------------
__global__ void logdet_kernel(const float* __restrict__ cW) {
    __shared__ float A[64][65];
    __shared__ int piv;
    int f = blockIdx.x;
    int tid = threadIdx.x;  // 64 threads
    for (int j = 0; j < 64; j++) A[j][tid] = cW[f * 4096 + j * 64 + tid];
    __syncthreads();
    for (int j = 0; j < 64; j++) {
        if (tid == 0) {
            int p = j;
            float mv = fabsf(A[j][j]);
            for (int i = j + 1; i < 64; i++) {
                float v = fabsf(A[i][j]);
                if (v > mv) { mv = v; p = i; }
            }
            piv = p;
        }
        __syncthreads();
        int p = piv;
        if (p != j) {
            float t = A[j][tid];
            A[j][tid] = A[p][tid];
            A[p][tid] = t;
        }
        __syncthreads();
        if (tid > j) {
            float fct = A[tid][j] / A[j][j];
            for (int k = j; k < 64; k++) A[tid][k] -= fct * A[j][k];
        }
        __syncthreads();
    }
    if (tid == 0) {
        float s = 0.f;
        for (int j = 0; j < 64; j++) s += logf(fabsf(A[j][j]));
        g_logdet[f] = s;
    }
}

__global__ void init_ldj_kernel(float* __restrict__ ldj) {
    if (threadIdx.x < 64) {
        float s = g_logdet[0] + g_logdet[1] + g_logdet[2] + g_logdet[3];
        ldj[threadIdx.x] = 2048.0f * s;
    }
}

// ---------------------------------------------------------------------------
// fused flow kernel: 32 tokens per block, 256 threads
// warp tm = token group (4 tokens), lane tn = column group (cols 2tn,2tn+1,...)
// smem: ze[32*64] | ext[32*64] | h[32*512] | stage[4096]
// ---------------------------------------------------------------------------
__global__ __launch_bounds__(256, 2) void flow_kernel(
    const float* __restrict__ zin, const int* __restrict__ categ,
    const float* __restrict__ embed, const float* __restrict__ aW,
    const float* __restrict__ ab, const float* __restrict__ cW,
    const float* __restrict__ scf, const float* __restrict__ W0,
    const float* __restrict__ b0, const float* __restrict__ W1,
    const float* __restrict__ b1, const float* __restrict__ W2,
    const float* __restrict__ b2, float* __restrict__ outz,
    float* __restrict__ ldj) {
    extern __shared__ float smem[];
    float* ze = smem;             // 2048 floats
    float* ext = smem + 2048;     // 2048 floats
    float* h = smem + 4096;       // 16384 floats
    float* stage = smem + 20480;  // 4096 floats
    __shared__ int cat[32];
    __shared__ float wsum[8];

    const int tid = threadIdx.x;
    const int tm = tid >> 5;
    const int tn = tid & 31;
    const int t0 = blockIdx.x * 32;
    const int m0 = tm * 4;

    // load z tile (32x64) and categories
    {
        const float4* zg = (const float4*)(zin + (long long)t0 * 64);
        float4* zs = (float4*)ze;
#pragma unroll
        for (int i = 0; i < 2; i++) zs[tid + 256 * i] = zg[tid + 256 * i];
    }
    if (tid < 32) cat[tid] = categ[t0 + tid];
    __syncthreads();
    // gather embeddings (32x64)
    {
        float4* es = (float4*)ext;
#pragma unroll
        for (int i = 0; i < 2; i++) {
            int idx = tid + 256 * i;
            int m = idx >> 4, e4 = idx & 15;
            es[idx] = ((const float4*)embed)[(long long)cat[m] * 16 + e4];
        }
    }
    float ldj_acc = 0.f;

#pragma unroll 1
    for (int f = 0; f < 4; f++) {
        const float* aWf = aW + f * 64 * 128;
        const float* abf = ab + f * 128;
        const float* cWf = cW + f * 64 * 64;
        const float* scff = scf + f * 64;
        const float* W0f = W0 + f * 128 * 512;
        const float* b0f = b0 + f * 512;
        const float* W1f = W1 + f * 512 * 512;
        const float* b1f = b1 + f * 512;
        const float* W2f = W2 + f * 512 * 128;
        const float* b2f = b2 + f * 128;

        // ========== G1: actnorm  nn = ext(32x64) @ aW(64x128) ==========
        {
            unsigned long long acc[4][2] = {{0ull, 0ull}, {0ull, 0ull}, {0ull, 0ull}, {0ull, 0ull}};
#pragma unroll 1
            for (int k0 = 0; k0 < 64; k0 += 32) {
                __syncthreads();
                copy4k(stage, aWf + k0 * 128, tid);
                __syncthreads();
#pragma unroll 4
                for (int kk = 0; kk < 32; kk++) {
                    const float* srow = stage + kk * 128 + 2 * tn;
                    unsigned long long w0 = *(const unsigned long long*)(srow);
                    unsigned long long w1 = *(const unsigned long long*)(srow + 64);
#pragma unroll
                    for (int i = 0; i < 4; i++) {
                        unsigned long long a = dup2(ext[(m0 + i) * 64 + k0 + kk]);
                        fma2(acc[i][0], a, w0);
                        fma2(acc[i][1], a, w1);
                    }
                }
            }
            __syncthreads();
            const int d0 = 2 * tn;
            const float ab0 = abf[d0], ab1 = abf[d0 + 1];
            const float as0 = abf[64 + d0], as1 = abf[65 + d0];
#pragma unroll
            for (int i = 0; i < 4; i++) {
                float2 bi = unpk(acc[i][0]);
                float2 sc = unpk(acc[i][1]);
                float s0 = tanhf(sc.x + as0);
                float s1 = tanhf(sc.y + as1);
                float* zp = ze + (m0 + i) * 64 + d0;
                zp[0] = (zp[0] + bi.x + ab0) * expf(s0);
                zp[1] = (zp[1] + bi.y + ab1) * expf(s1);
                ldj_acc += s0 + s1;
            }
            __syncthreads();
        }

        // ========== G2: conv  z = z(32x64) @ cW(64x64) ==========
        {
            unsigned long long acc[4] = {0ull, 0ull, 0ull, 0ull};
            copy4k(stage, cWf, tid);
            __syncthreads();
#pragma unroll 4
            for (int kk = 0; kk < 64; kk++) {
                unsigned long long w = *(const unsigned long long*)(stage + kk * 64 + 2 * tn);
#pragma unroll
                for (int i = 0; i < 4; i++) {
                    unsigned long long a = dup2(ze[(m0 + i) * 64 + kk]);
                    fma2(acc[i], a, w);
                }
            }
            __syncthreads();
#pragma unroll
            for (int i = 0; i < 4; i++) {
                float2 v = unpk(acc[i]);
                ze[(m0 + i) * 64 + 2 * tn] = v.x;
                ze[(m0 + i) * 64 + 2 * tn + 1] = v.y;
            }
            __syncthreads();
        }

        // ========== G3: h = gelu([z*mask, ext](32x128) @ W0(128x512) + b0) ==
        // mask zeroes z cols 32..63 -> skip W0 rows 32..63 entirely.
        {
            unsigned long long acc[4][8];
#pragma unroll
            for (int i = 0; i < 4; i++)
#pragma unroll
                for (int j = 0; j < 8; j++) acc[i][j] = 0ull;
#pragma unroll 1
            for (int half = 0; half < 2; half++) {
                const float* Abase = half ? ext : ze;
                const int kmax = half ? 64 : 32;
                const int krow0 = half ? 64 : 0;
#pragma unroll 1
                for (int k0 = 0; k0 < kmax; k0 += 8) {
                    __syncthreads();
                    copy4k(stage, W0f + (krow0 + k0) * 512, tid);
                    __syncthreads();
#pragma unroll
                    for (int kk = 0; kk < 8; kk++) {
                        unsigned long long a0 = dup2(Abase[(m0 + 0) * 64 + k0 + kk]);
                        unsigned long long a1 = dup2(Abase[(m0 + 1) * 64 + k0 + kk]);
                        unsigned long long a2 = dup2(Abase[(m0 + 2) * 64 + k0 + kk]);
                        unsigned long long a3 = dup2(Abase[(m0 + 3) * 64 + k0 + kk]);
                        const float* srow = stage + kk * 512 + 2 * tn;
#pragma unroll
                        for (int j = 0; j < 8; j++) {
                            unsigned long long w = *(const unsigned long long*)(srow + 64 * j);
                            fma2(acc[0][j], a0, w);
                            fma2(acc[1][j], a1, w);
                            fma2(acc[2][j], a2, w);
                            fma2(acc[3][j], a3, w);
                        }
                    }
                }
            }
            __syncthreads();
#pragma unroll
            for (int i = 0; i < 4; i++) {
#pragma unroll
                for (int j = 0; j < 8; j++) {
                    int n = 2 * tn + 64 * j;
                    float2 v = unpk(acc[i][j]);
                    h[(m0 + i) * 512 + n] = gelu_exact(v.x + b0f[n]);
                    h[(m0 + i) * 512 + n + 1] = gelu_exact(v.y + b0f[n + 1]);
                }
            }
            __syncthreads();
        }

        // ========== G4: h = gelu(h(32x512) @ W1(512x512) + b1)  (in place) ==
        {
            unsigned long long acc[4][8];
#pragma unroll
            for (int i = 0; i < 4; i++)
#pragma unroll
                for (int j = 0; j < 8; j++) acc[i][j] = 0ull;
#pragma unroll 1
            for (int k0 = 0; k0 < 512; k0 += 8) {
                __syncthreads();
                copy4k(stage, W1f + k0 * 512, tid);
                __syncthreads();
#pragma unroll
                for (int kk = 0; kk < 8; kk++) {
                    unsigned long long a0 = dup2(h[(m0 + 0) * 512 + k0 + kk]);
                    unsigned long long a1 = dup2(h[(m0 + 1) * 512 + k0 + kk]);
                    unsigned long long a2 = dup2(h[(m0 + 2) * 512 + k0 + kk]);
                    unsigned long long a3 = dup2(h[(m0 + 3) * 512 + k0 + kk]);
                    const float* srow = stage + kk * 512 + 2 * tn;
#pragma unroll
                    for (int j = 0; j < 8; j++) {
                        unsigned long long w = *(const unsigned long long*)(srow + 64 * j);
                        fma2(acc[0][j], a0, w);
                        fma2(acc[1][j], a1, w);
                        fma2(acc[2][j], a2, w);
                        fma2(acc[3][j], a3, w);
                    }
                }
            }
            __syncthreads();  // all reads of h done before overwrite
#pragma unroll
            for (int i = 0; i < 4; i++) {
#pragma unroll
                for (int j = 0; j < 8; j++) {
                    int n = 2 * tn + 64 * j;
                    float2 v = unpk(acc[i][j]);
                    h[(m0 + i) * 512 + n] = gelu_exact(v.x + b1f[n]);
                    h[(m0 + i) * 512 + n + 1] = gelu_exact(v.y + b1f[n + 1]);
                }
            }
            __syncthreads();
        }

        // ========== G5: coupling. Only output cols 64..127 of W2 matter ====
        // (s,t for d<32 are masked to zero -> z unchanged there)
        {
            unsigned long long acc[4] = {0ull, 0ull, 0ull, 0ull};
#pragma unroll 1
            for (int k0 = 0; k0 < 512; k0 += 32) {
                __syncthreads();
                copy4k(stage, W2f + k0 * 128, tid);
                __syncthreads();
#pragma unroll 4
                for (int kk = 0; kk < 32; kk++) {
                    unsigned long long w =
                        *(const unsigned long long*)(stage + kk * 128 + 64 + 2 * tn);
#pragma unroll
                    for (int i = 0; i < 4; i++) {
                        unsigned long long a = dup2(h[(m0 + i) * 512 + k0 + kk]);
                        fma2(acc[i], a, w);
                    }
                }
            }
            __syncthreads();
            const int d = 32 + tn;  // s = col 2d = 64+2tn, t = col 2d+1
            const float sf = expf(scff[d]);
            const float den = fmaxf(sf, 1.0f);
            const float bs = b2f[64 + 2 * tn];
            const float bt = b2f[65 + 2 * tn];
#pragma unroll
            for (int i = 0; i < 4; i++) {
                float2 v = unpk(acc[i]);
                float s = tanhf((v.x + bs) / den) * sf;
                float tt = v.y + bt;
                float* zp = ze + (m0 + i) * 64 + d;
                zp[0] = (zp[0] + tt) * expf(s);
                ldj_acc += s;
            }
            __syncthreads();
        }
    }  // flows

    // write z tile out
    {
        float4* og = (float4*)(outz + (long long)t0 * 64);
        const float4* zs = (const float4*)ze;
#pragma unroll
        for (int i = 0; i < 2; i++) og[tid + 256 * i] = zs[tid + 256 * i];
    }
    // ldj: block reduce + atomic into per-batch slot
#pragma unroll
    for (int o = 16; o; o >>= 1) ldj_acc += __shfl_xor_sync(0xffffffffu, ldj_acc, o);
    if (tn == 0) wsum[tm] = ldj_acc;
    __syncthreads();
    if (tid == 0) {
        float s = 0.f;
#pragma unroll
        for (int i = 0; i < 8; i++) s += wsum[i];
        atomicAdd(&ldj[blockIdx.x >> 6], s);  // 64 blocks per batch
    }
}

// ---------------------------------------------------------------------------
extern "C" void kernel_launch(void* const* d_in, const int* in_sizes, int n_in,
                              void* d_out, int out_size) {
    const float* z = (const float*)d_in[0];
    const int* categ = (const int*)d_in[1];
    const float* embed = (const float*)d_in[2];
    const float* actnorm_W = (const float*)d_in[3];
    const float* actnorm_b = (const float*)d_in[4];
    const float* conv_W = (const float*)d_in[5];
    const float* scaling_factor = (const float*)d_in[6];
    const float* W0 = (const float*)d_in[7];
    const float* b0 = (const float*)d_in[8];
    const float* W1 = (const float*)d_in[9];
    const float* b1 = (const float*)d_in[10];
    const float* W2 = (const float*)d_in[11];
    const float* b2 = (const float*)d_in[12];

    float* outz = (float*)d_out;
    float* ldj = outz + (long long)TOKENS * 64;

    static const int SMEM_BYTES = 24576 * sizeof(float);  // 98304
    cudaFuncSetAttribute(flow_kernel, cudaFuncAttributeMaxDynamicSharedMemorySize,
                         SMEM_BYTES);

    logdet_kernel<<<4, 64>>>(conv_W);
    init_ldj_kernel<<<1, 64>>>(ldj);
    flow_kernel<<<NBLOCKS, 256, SMEM_BYTES>>>(z, categ, embed, actnorm_W, actnorm_b,
                                              conv_W, scaling_factor, W0, b0, W1, b1,
                                              W2, b2, outz, ldj);
}

// round 3
// speedup vs baseline: 1.0007x; 1.0007x over previous
#include <cuda_runtime.h>

// Problem constants
// B=64, S=2048, D=64, E=64, H=512, F=4, V=32000
#define TOKENS (64 * 2048)
#define NBLOCKS (TOKENS / 32)

__device__ float g_logdet[4];

// ---------------------------------------------------------------------------
// helpers
// ---------------------------------------------------------------------------
__device__ __forceinline__ unsigned long long dup2(float a) {
    unsigned long long r;
    unsigned int ai = __float_as_uint(a);
    asm("mov.b64 %0, {%1, %1};" : "=l"(r) : "r"(ai));
    return r;
}
__device__ __forceinline__ void fma2(unsigned long long& d, unsigned long long a,
                                     unsigned long long b) {
    asm("fma.rn.f32x2 %0, %1, %2, %0;" : "+l"(d) : "l"(a), "l"(b));
}
__device__ __forceinline__ float2 unpk(unsigned long long v) {
    unsigned int lo, hi;
    asm("mov.b64 {%0, %1}, %2;" : "=r"(lo), "=r"(hi) : "l"(v));
    float2 r;
    r.x = __uint_as_float(lo);
    r.y = __uint_as_float(hi);
    return r;
}
__device__ __forceinline__ float gelu_exact(float x) {
    return 0.5f * x * (1.0f + erff(x * 0.70710678118654752440f));
}
// copy 4096 floats (16KB) global -> smem, 256 threads, float4
__device__ __forceinline__ void copy4k(float* dst, const float* src, int tid) {
    const float4* s = (const float4*)src;
    float4* d = (float4*)dst;
#pragma unroll
    for (int i = 0; i < 4; i++) d[tid + 256 * i] = s[tid + 256 * i];
}

// ---------------------------------------------------------------------------
// slogdet of the 4 conv matrices (64x64 LU w/ partial pivoting)
// ---------------------------------------------------------------------------
__global__ void logdet_kernel(const float* __restrict__ cW) {
    __shared__ float A[64][65];
    __shared__ int piv;
    int f = blockIdx.x;
    int tid = threadIdx.x;  // 64 threads
    for (int j = 0; j < 64; j++) A[j][tid] = cW[f * 4096 + j * 64 + tid];
    __syncthreads();
    for (int j = 0; j < 64; j++) {
        if (tid == 0) {
            int p = j;
            float mv = fabsf(A[j][j]);
            for (int i = j + 1; i < 64; i++) {
                float v = fabsf(A[i][j]);
                if (v > mv) { mv = v; p = i; }
            }
            piv = p;
        }
        __syncthreads();
        int p = piv;
        if (p != j) {
            float t = A[j][tid];
            A[j][tid] = A[p][tid];
            A[p][tid] = t;
        }
        __syncthreads();
        if (tid > j) {
            float fct = A[tid][j] / A[j][j];
            for (int k = j; k < 64; k++) A[tid][k] -= fct * A[j][k];
        }
        __syncthreads();
    }
    if (tid == 0) {
        float s = 0.f;
        for (int j = 0; j < 64; j++) s += logf(fabsf(A[j][j]));
        g_logdet[f] = s;
    }
}

__global__ void init_ldj_kernel(float* __restrict__ ldj) {
    if (threadIdx.x < 64) {
        float s = g_logdet[0] + g_logdet[1] + g_logdet[2] + g_logdet[3];
        ldj[threadIdx.x] = 2048.0f * s;
    }
}

// ---------------------------------------------------------------------------
// fused flow kernel: 32 tokens per block, 256 threads
// warp tm = token group (4 tokens), lane tn = column group (cols 2tn,2tn+1,...)
// smem: ze[32*64] | ext[32*64] | h[32*512] | stage[4096]
// ---------------------------------------------------------------------------
__global__ __launch_bounds__(256, 2) void flow_kernel(
    const float* __restrict__ zin, const int* __restrict__ categ,
    const float* __restrict__ embed, const float* __restrict__ aW,
    const float* __restrict__ ab, const float* __restrict__ cW,
    const float* __restrict__ scf, const float* __restrict__ W0,
    const float* __restrict__ b0, const float* __restrict__ W1,
    const float* __restrict__ b1, const float* __restrict__ W2,
    const float* __restrict__ b2, float* __restrict__ outz,
    float* __restrict__ ldj) {
    extern __shared__ float smem[];
    float* ze = smem;             // 2048 floats
    float* ext = smem + 2048;     // 2048 floats
    float* h = smem + 4096;       // 16384 floats
    float* stage = smem + 20480;  // 4096 floats
    __shared__ int cat[32];
    __shared__ float wsum[8];

    const int tid = threadIdx.x;
    const int tm = tid >> 5;
    const int tn = tid & 31;
    const int t0 = blockIdx.x * 32;
    const int m0 = tm * 4;

    // load z tile (32x64) and categories
    {
        const float4* zg = (const float4*)(zin + (long long)t0 * 64);
        float4* zs = (float4*)ze;
#pragma unroll
        for (int i = 0; i < 2; i++) zs[tid + 256 * i] = zg[tid + 256 * i];
    }
    if (tid < 32) cat[tid] = categ[t0 + tid];
    __syncthreads();
    // gather embeddings (32x64)
    {
        float4* es = (float4*)ext;
#pragma unroll
        for (int i = 0; i < 2; i++) {
            int idx = tid + 256 * i;
            int m = idx >> 4, e4 = idx & 15;
            es[idx] = ((const float4*)embed)[(long long)cat[m] * 16 + e4];
        }
    }
    float ldj_acc = 0.f;

#pragma unroll 1
    for (int f = 0; f < 4; f++) {
        const float* aWf = aW + f * 64 * 128;
        const float* abf = ab + f * 128;
        const float* cWf = cW + f * 64 * 64;
        const float* scff = scf + f * 64;
        const float* W0f = W0 + f * 128 * 512;
        const float* b0f = b0 + f * 512;
        const float* W1f = W1 + f * 512 * 512;
        const float* b1f = b1 + f * 512;
        const float* W2f = W2 + f * 512 * 128;
        const float* b2f = b2 + f * 128;

        // ========== G1: actnorm  nn = ext(32x64) @ aW(64x128) ==========
        {
            unsigned long long acc[4][2] = {{0ull, 0ull}, {0ull, 0ull}, {0ull, 0ull}, {0ull, 0ull}};
#pragma unroll 1
            for (int k0 = 0; k0 < 64; k0 += 32) {
                __syncthreads();
                copy4k(stage, aWf + k0 * 128, tid);
                __syncthreads();
#pragma unroll 4
                for (int kk = 0; kk < 32; kk++) {
                    const float* srow = stage + kk * 128 + 2 * tn;
                    unsigned long long w0 = *(const unsigned long long*)(srow);
                    unsigned long long w1 = *(const unsigned long long*)(srow + 64);
#pragma unroll
                    for (int i = 0; i < 4; i++) {
                        unsigned long long a = dup2(ext[(m0 + i) * 64 + k0 + kk]);
                        fma2(acc[i][0], a, w0);
                        fma2(acc[i][1], a, w1);
                    }
                }
            }
            __syncthreads();
            const int d0 = 2 * tn;
            const float ab0 = abf[d0], ab1 = abf[d0 + 1];
            const float as0 = abf[64 + d0], as1 = abf[65 + d0];
#pragma unroll
            for (int i = 0; i < 4; i++) {
                float2 bi = unpk(acc[i][0]);
                float2 sc = unpk(acc[i][1]);
                float s0 = tanhf(sc.x + as0);
                float s1 = tanhf(sc.y + as1);
                float* zp = ze + (m0 + i) * 64 + d0;
                zp[0] = (zp[0] + bi.x + ab0) * expf(s0);
                zp[1] = (zp[1] + bi.y + ab1) * expf(s1);
                ldj_acc += s0 + s1;
            }
            __syncthreads();
        }

        // ========== G2: conv  z = z(32x64) @ cW(64x64) ==========
        {
            unsigned long long acc[4] = {0ull, 0ull, 0ull, 0ull};
            copy4k(stage, cWf, tid);
            __syncthreads();
#pragma unroll 4
            for (int kk = 0; kk < 64; kk++) {
                unsigned long long w = *(const unsigned long long*)(stage + kk * 64 + 2 * tn);
#pragma unroll
                for (int i = 0; i < 4; i++) {
                    unsigned long long a = dup2(ze[(m0 + i) * 64 + kk]);
                    fma2(acc[i], a, w);
                }
            }
            __syncthreads();
#pragma unroll
            for (int i = 0; i < 4; i++) {
                float2 v = unpk(acc[i]);
                ze[(m0 + i) * 64 + 2 * tn] = v.x;
                ze[(m0 + i) * 64 + 2 * tn + 1] = v.y;
            }
            __syncthreads();
        }

        // ========== G3: h = gelu([z*mask, ext](32x128) @ W0(128x512) + b0) ==
        // mask zeroes z cols 32..63 -> skip W0 rows 32..63 entirely.
        {
            unsigned long long acc[4][8];
#pragma unroll
            for (int i = 0; i < 4; i++)
#pragma unroll
                for (int j = 0; j < 8; j++) acc[i][j] = 0ull;
#pragma unroll 1
            for (int half = 0; half < 2; half++) {
                const float* Abase = half ? ext : ze;
                const int kmax = half ? 64 : 32;
                const int krow0 = half ? 64 : 0;
#pragma unroll 1
                for (int k0 = 0; k0 < kmax; k0 += 8) {
                    __syncthreads();
                    copy4k(stage, W0f + (krow0 + k0) * 512, tid);
                    __syncthreads();
#pragma unroll
                    for (int kk = 0; kk < 8; kk++) {
                        unsigned long long a0 = dup2(Abase[(m0 + 0) * 64 + k0 + kk]);
                        unsigned long long a1 = dup2(Abase[(m0 + 1) * 64 + k0 + kk]);
                        unsigned long long a2 = dup2(Abase[(m0 + 2) * 64 + k0 + kk]);
                        unsigned long long a3 = dup2(Abase[(m0 + 3) * 64 + k0 + kk]);
                        const float* srow = stage + kk * 512 + 2 * tn;
#pragma unroll
                        for (int j = 0; j < 8; j++) {
                            unsigned long long w = *(const unsigned long long*)(srow + 64 * j);
                            fma2(acc[0][j], a0, w);
                            fma2(acc[1][j], a1, w);
                            fma2(acc[2][j], a2, w);
                            fma2(acc[3][j], a3, w);
                        }
                    }
                }
            }
            __syncthreads();
#pragma unroll
            for (int i = 0; i < 4; i++) {
#pragma unroll
                for (int j = 0; j < 8; j++) {
                    int n = 2 * tn + 64 * j;
                    float2 v = unpk(acc[i][j]);
                    h[(m0 + i) * 512 + n] = gelu_exact(v.x + b0f[n]);
                    h[(m0 + i) * 512 + n + 1] = gelu_exact(v.y + b0f[n + 1]);
                }
            }
            __syncthreads();
        }

        // ========== G4: h = gelu(h(32x512) @ W1(512x512) + b1)  (in place) ==
        {
            unsigned long long acc[4][8];
#pragma unroll
            for (int i = 0; i < 4; i++)
#pragma unroll
                for (int j = 0; j < 8; j++) acc[i][j] = 0ull;
#pragma unroll 1
            for (int k0 = 0; k0 < 512; k0 += 8) {
                __syncthreads();
                copy4k(stage, W1f + k0 * 512, tid);
                __syncthreads();
#pragma unroll
                for (int kk = 0; kk < 8; kk++) {
                    unsigned long long a0 = dup2(h[(m0 + 0) * 512 + k0 + kk]);
                    unsigned long long a1 = dup2(h[(m0 + 1) * 512 + k0 + kk]);
                    unsigned long long a2 = dup2(h[(m0 + 2) * 512 + k0 + kk]);
                    unsigned long long a3 = dup2(h[(m0 + 3) * 512 + k0 + kk]);
                    const float* srow = stage + kk * 512 + 2 * tn;
#pragma unroll
                    for (int j = 0; j < 8; j++) {
                        unsigned long long w = *(const unsigned long long*)(srow + 64 * j);
                        fma2(acc[0][j], a0, w);
                        fma2(acc[1][j], a1, w);
                        fma2(acc[2][j], a2, w);
                        fma2(acc[3][j], a3, w);
                    }
                }
            }
            __syncthreads();  // all reads of h done before overwrite
#pragma unroll
            for (int i = 0; i < 4; i++) {
#pragma unroll
                for (int j = 0; j < 8; j++) {
                    int n = 2 * tn + 64 * j;
                    float2 v = unpk(acc[i][j]);
                    h[(m0 + i) * 512 + n] = gelu_exact(v.x + b1f[n]);
                    h[(m0 + i) * 512 + n + 1] = gelu_exact(v.y + b1f[n + 1]);
                }
            }
            __syncthreads();
        }

        // ========== G5: coupling. Only output cols 64..127 of W2 matter ====
        // (s,t for d<32 are masked to zero -> z unchanged there)
        {
            unsigned long long acc[4] = {0ull, 0ull, 0ull, 0ull};
#pragma unroll 1
            for (int k0 = 0; k0 < 512; k0 += 32) {
                __syncthreads();
                copy4k(stage, W2f + k0 * 128, tid);
                __syncthreads();
#pragma unroll 4
                for (int kk = 0; kk < 32; kk++) {
                    unsigned long long w =
                        *(const unsigned long long*)(stage + kk * 128 + 64 + 2 * tn);
#pragma unroll
                    for (int i = 0; i < 4; i++) {
                        unsigned long long a = dup2(h[(m0 + i) * 512 + k0 + kk]);
                        fma2(acc[i], a, w);
                    }
                }
            }
            __syncthreads();
            const int d = 32 + tn;  // s = col 2d = 64+2tn, t = col 2d+1
            const float sf = expf(scff[d]);
            const float den = fmaxf(sf, 1.0f);
            const float bs = b2f[64 + 2 * tn];
            const float bt = b2f[65 + 2 * tn];
#pragma unroll
            for (int i = 0; i < 4; i++) {
                float2 v = unpk(acc[i]);
                float s = tanhf((v.x + bs) / den) * sf;
                float tt = v.y + bt;
                float* zp = ze + (m0 + i) * 64 + d;
                zp[0] = (zp[0] + tt) * expf(s);
                ldj_acc += s;
            }
            __syncthreads();
        }
    }  // flows

    // write z tile out
    {
        float4* og = (float4*)(outz + (long long)t0 * 64);
        const float4* zs = (const float4*)ze;
#pragma unroll
        for (int i = 0; i < 2; i++) og[tid + 256 * i] = zs[tid + 256 * i];
    }
    // ldj: block reduce + atomic into per-batch slot
#pragma unroll
    for (int o = 16; o; o >>= 1) ldj_acc += __shfl_xor_sync(0xffffffffu, ldj_acc, o);
    if (tn == 0) wsum[tm] = ldj_acc;
    __syncthreads();
    if (tid == 0) {
        float s = 0.f;
#pragma unroll
        for (int i = 0; i < 8; i++) s += wsum[i];
        atomicAdd(&ldj[blockIdx.x >> 6], s);  // 64 blocks per batch
    }
}

// ---------------------------------------------------------------------------
extern "C" void kernel_launch(void* const* d_in, const int* in_sizes, int n_in,
                              void* d_out, int out_size) {
    const float* z = (const float*)d_in[0];
    const int* categ = (const int*)d_in[1];
    const float* embed = (const float*)d_in[2];
    const float* actnorm_W = (const float*)d_in[3];
    const float* actnorm_b = (const float*)d_in[4];
    const float* conv_W = (const float*)d_in[5];
    const float* scaling_factor = (const float*)d_in[6];
    const float* W0 = (const float*)d_in[7];
    const float* b0 = (const float*)d_in[8];
    const float* W1 = (const float*)d_in[9];
    const float* b1 = (const float*)d_in[10];
    const float* W2 = (const float*)d_in[11];
    const float* b2 = (const float*)d_in[12];

    float* outz = (float*)d_out;
    float* ldj = outz + (long long)TOKENS * 64;

    static const int SMEM_BYTES = 24576 * sizeof(float);  // 98304
    cudaFuncSetAttribute(flow_kernel, cudaFuncAttributeMaxDynamicSharedMemorySize,
                         SMEM_BYTES);

    logdet_kernel<<<4, 64>>>(conv_W);
    init_ldj_kernel<<<1, 64>>>(ldj);
    flow_kernel<<<NBLOCKS, 256, SMEM_BYTES>>>(z, categ, embed, actnorm_W, actnorm_b,
                                              conv_W, scaling_factor, W0, b0, W1, b1,
                                              W2, b2, outz, ldj);
}